// round 7
// baseline (speedup 1.0000x reference)
#include <cuda_runtime.h>
#include <cuda_fp16.h>
#include <mma.h>
#include <cstddef>
#include <cstdint>
using namespace nvcuda;

#define NN 100000
#define EE 3200000
#define NPAD 100096            // 782 * 128
#define SCAN_B 98              // ceil(NN/1024)

// ---------------- scratch (device globals; zero-initialized) ----------------
__device__ __half g_Xh[(size_t)NPAD * 512];   // fp16 copy of x (padded rows = 0)
__device__ __half g_T0h[(size_t)NPAD * 256];  // x@W1 ; reused as [NPAD,64] for gc3
__device__ __half g_H1h[(size_t)NPAD * 256];  // relu(spmm1 + b1)
__device__ __half g_T1h[(size_t)NPAD * 64];   // H1@W2
__device__ __half g_H3h[(size_t)NPAD * 64];   // spmm2 + b2
__device__ __half g_W1h[512 * 256];
__device__ __half g_W2h[256 * 64];
__device__ __half g_W3h[64 * 64];
__device__ int    g_deg[NN];
__device__ int    g_incl[SCAN_B * 1024];
__device__ int    g_part[SCAN_B + 1];
__device__ int    g_rowptr[NN + 1];
__device__ int    g_wofs[NN];
__device__ int2   g_edge[EE];                 // {src, weight-bits}

// ------------------------------ helpers ------------------------------------
__device__ __forceinline__ void cp16(void* s, const void* g) {
    uint32_t sa = (uint32_t)__cvta_generic_to_shared(s);
    asm volatile("cp.async.cg.shared.global [%0], [%1], 16;" :: "r"(sa), "l"(g));
}
__device__ __forceinline__ void cp_commit() {
    asm volatile("cp.async.commit_group;");
}
template <int P>
__device__ __forceinline__ void cp_wait() {
    asm volatile("cp.async.wait_group %0;" :: "n"(P));
}

__device__ __forceinline__ void f2h_unit(const float4* __restrict__ in,
                                         __half* __restrict__ out, int unit) {
    size_t i = (size_t)unit * 256 + threadIdx.x;
    float4 v = in[i];
    __half2* o = (__half2*)(out + i * 4);
    o[0] = __floats2half2_rn(v.x, v.y);
    o[1] = __floats2half2_rn(v.z, v.w);
}

// ---------------------------------------------------------------------------
// fused_front: edge histogram (CSR phase 1)  ∥  fp32->fp16 conversions.
// grid = 62685.  bx%5==0 -> hist block hb=bx/5 (<12500);
// else conv unit cid=(bx/5)*4+(bx%5-1):
//   [0,50000)      x      (12.8M float4)
//   [50000,50128)  W1     (32768 float4)
//   [50128,50144)  W2     (4096 float4)
//   [50144,50148)  W3     (1024 float4)
// ---------------------------------------------------------------------------
__global__ void fused_front(const int* __restrict__ dst, int* __restrict__ deg,
                            const float4* __restrict__ x4, __half* __restrict__ xh,
                            const float4* __restrict__ w1, __half* __restrict__ w1h,
                            const float4* __restrict__ w2, __half* __restrict__ w2h,
                            const float4* __restrict__ w3, __half* __restrict__ w3h) {
    int bx = blockIdx.x;
    if (bx % 5 == 0) {
        int hb = bx / 5;
        if (hb < 12500) {
            int i = hb * 256 + threadIdx.x;
            atomicAdd(&deg[dst[i]], 1);
        }
    } else {
        int cid = (bx / 5) * 4 + (bx % 5) - 1;
        if (cid < 50000) {
            f2h_unit(x4, xh, cid);
        } else if (cid < 50128) {
            f2h_unit(w1, w1h, cid - 50000);
        } else if (cid < 50144) {
            f2h_unit(w2, w2h, cid - 50128);
        } else {
            f2h_unit(w3, w3h, cid - 50144);
        }
    }
}

// ---------------------------- CSR scan kernels ------------------------------
__global__ void scan_block(const int* __restrict__ deg, int* __restrict__ incl,
                           int* __restrict__ part) {
    __shared__ int s[1024];
    int tid = threadIdx.x;
    int i = blockIdx.x * 1024 + tid;
    int v = (i < NN) ? deg[i] : 0;
    s[tid] = v;
    __syncthreads();
#pragma unroll
    for (int o = 1; o < 1024; o <<= 1) {
        int t = (tid >= o) ? s[tid - o] : 0;
        __syncthreads();
        if (tid >= o) s[tid] += t;
        __syncthreads();
    }
    incl[i] = s[tid];
    if (tid == 1023) part[blockIdx.x] = s[1023];
}

__global__ void scan_partials(int* __restrict__ part) {
    if (threadIdx.x == 0) {
        int run = 0;
        for (int i = 0; i < SCAN_B; i++) {
            int t = part[i];
            part[i] = run;
            run += t;
        }
    }
}

__global__ void scan_finalize(const int* __restrict__ deg, const int* __restrict__ incl,
                              const int* __restrict__ part, int* __restrict__ rowptr,
                              int* __restrict__ wofs) {
    int i = blockIdx.x * blockDim.x + threadIdx.x;
    if (i < NN) {
        int excl = incl[i] - deg[i] + part[i >> 10];
        rowptr[i] = excl;
        wofs[i] = excl;
    }
    if (i == 0) rowptr[NN] = EE;
}

// ---------------------------------------------------------------------------
// fused_sg: edge scatter (CSR phase 3)  ∥  GEMM1 (wmma fp16, 128x128 tiles).
// grid = 14076.  bx%9==0 -> gemm gid=bx/9 in [0,1564): row0=(gid>>1)*128,
// col0=(gid&1)*128.  Else scatter sid=(bx/9)*8+(bx%9)-1, guard sid<12500.
// GEMM: C[NPAD,256] = A[NPAD,512] @ B[512,256], all fp16, f32 accum.
// ---------------------------------------------------------------------------
__global__ void __launch_bounds__(256, 2)
fused_sg(const int* __restrict__ src, const int* __restrict__ dst,
         const float* __restrict__ w, int* __restrict__ wofs, int2* __restrict__ edge,
         const __half* __restrict__ A, const __half* __restrict__ B,
         __half* __restrict__ C) {
    constexpr int SA = 40;
    constexpr int SB = 136;
    __shared__ __half As[2][128 * SA];
    __shared__ __half Bs[2][32 * SB];

    int bx = blockIdx.x;
    if (bx % 9 != 0) {
        int sid = (bx / 9) * 8 + (bx % 9) - 1;
        if (sid < 12500) {
            int i = sid * 256 + threadIdx.x;
            int pos = atomicAdd(&wofs[dst[i]], 1);
            edge[pos] = make_int2(src[i], __float_as_int(w[i]));
        }
        return;
    }
    const int gid = bx / 9;
    const int tid = threadIdx.x;
    const int wid = tid >> 5;
    const int wm = wid & 3;
    const int wn = wid >> 2;
    const int row0 = (gid >> 1) * 128;
    const int col0 = (gid & 1) * 128;
    const int K = 512, N = 256;

    const int ar = tid >> 2;
    const int ac = (tid & 3) * 8;

    wmma::fragment<wmma::accumulator, 16, 16, 16, float> acc[2][4];
#pragma unroll
    for (int i = 0; i < 2; i++)
#pragma unroll
        for (int j = 0; j < 4; j++) wmma::fill_fragment(acc[i][j], 0.0f);

    auto issue = [&](int buf, int k0) {
        const __half* Ag = A + (size_t)(row0 + ar) * K + k0 + ac;
        cp16(&As[buf][ar * SA + ac], Ag);
        cp16(&As[buf][(ar + 64) * SA + ac], Ag + (size_t)64 * K);
        int br = tid >> 4, bc = (tid & 15) * 8;
        cp16(&Bs[buf][br * SB + bc], B + (size_t)(k0 + br) * N + col0 + bc);
        cp16(&Bs[buf][(br + 16) * SB + bc], B + (size_t)(k0 + br + 16) * N + col0 + bc);
    };

    issue(0, 0);
    cp_commit();

    const int KT = K / 32;   // 16
    for (int kt = 0; kt < KT; kt++) {
        int buf = kt & 1;
        if (kt + 1 < KT) {
            issue(buf ^ 1, (kt + 1) * 32);
            cp_commit();
            cp_wait<1>();
        } else {
            cp_wait<0>();
        }
        __syncthreads();
#pragma unroll
        for (int kk = 0; kk < 32; kk += 16) {
            wmma::fragment<wmma::matrix_a, 16, 16, 16, __half, wmma::row_major> fa[2];
            wmma::fragment<wmma::matrix_b, 16, 16, 16, __half, wmma::row_major> fb[4];
#pragma unroll
            for (int i = 0; i < 2; i++)
                wmma::load_matrix_sync(fa[i], &As[buf][(wm * 32 + i * 16) * SA + kk], SA);
#pragma unroll
            for (int j = 0; j < 4; j++)
                wmma::load_matrix_sync(fb[j], &Bs[buf][kk * SB + wn * 64 + j * 16], SB);
#pragma unroll
            for (int i = 0; i < 2; i++)
#pragma unroll
                for (int j = 0; j < 4; j++)
                    wmma::mma_sync(acc[i][j], fa[i], fb[j], acc[i][j]);
        }
        __syncthreads();
    }

#pragma unroll
    for (int i = 0; i < 2; i++) {
        int r = row0 + wm * 32 + i * 16;
#pragma unroll
        for (int j = 0; j < 4; j++) {
            wmma::fragment<wmma::accumulator, 16, 16, 16, __half> hf;
#pragma unroll
            for (int t = 0; t < hf.num_elements; t++)
                hf.x[t] = __float2half(acc[i][j].x[t]);
            wmma::store_matrix_sync(C + (size_t)r * N + col0 + wn * 64 + j * 16,
                                    hf, N, wmma::mem_row_major);
        }
    }
}

// ---------------------------------------------------------------------------
// fp16 wmma GEMM (BN=64) with cp.async double buffering — GEMM2/GEMM3.
// ---------------------------------------------------------------------------
__launch_bounds__(256, 2)
__global__ void gemm_h64(const __half* __restrict__ A, const __half* __restrict__ B,
                         __half* __restrict__ C, int K, int N) {
    constexpr int SA = 40;
    constexpr int SB = 72;
    __shared__ __half As[2][128 * SA];
    __shared__ __half Bs[2][32 * SB];

    const int tid = threadIdx.x;
    const int wid = tid >> 5;
    const int wm = wid & 3;
    const int wn = wid >> 2;
    const int row0 = blockIdx.x * 128;
    const int col0 = 0;

    const int ar = tid >> 2;
    const int ac = (tid & 3) * 8;

    wmma::fragment<wmma::accumulator, 16, 16, 16, float> acc[2][2];
#pragma unroll
    for (int i = 0; i < 2; i++)
#pragma unroll
        for (int j = 0; j < 2; j++) wmma::fill_fragment(acc[i][j], 0.0f);

    const int KT = K / 32;

    auto issue = [&](int buf, int k0) {
        const __half* Ag = A + (size_t)(row0 + ar) * K + k0 + ac;
        cp16(&As[buf][ar * SA + ac], Ag);
        cp16(&As[buf][(ar + 64) * SA + ac], Ag + (size_t)64 * K);
        int br = tid >> 3, bc = (tid & 7) * 8;
        cp16(&Bs[buf][br * SB + bc], B + (size_t)(k0 + br) * N + col0 + bc);
    };

    issue(0, 0);
    cp_commit();

    for (int kt = 0; kt < KT; kt++) {
        int buf = kt & 1;
        if (kt + 1 < KT) {
            issue(buf ^ 1, (kt + 1) * 32);
            cp_commit();
            cp_wait<1>();
        } else {
            cp_wait<0>();
        }
        __syncthreads();
#pragma unroll
        for (int kk = 0; kk < 32; kk += 16) {
            wmma::fragment<wmma::matrix_a, 16, 16, 16, __half, wmma::row_major> fa[2];
            wmma::fragment<wmma::matrix_b, 16, 16, 16, __half, wmma::row_major> fb[2];
#pragma unroll
            for (int i = 0; i < 2; i++)
                wmma::load_matrix_sync(fa[i], &As[buf][(wm * 32 + i * 16) * SA + kk], SA);
#pragma unroll
            for (int j = 0; j < 2; j++)
                wmma::load_matrix_sync(fb[j], &Bs[buf][kk * SB + wn * 32 + j * 16], SB);
#pragma unroll
            for (int i = 0; i < 2; i++)
#pragma unroll
                for (int j = 0; j < 2; j++)
                    wmma::mma_sync(acc[i][j], fa[i], fb[j], acc[i][j]);
        }
        __syncthreads();
    }

#pragma unroll
    for (int i = 0; i < 2; i++) {
        int r = row0 + wm * 32 + i * 16;
#pragma unroll
        for (int j = 0; j < 2; j++) {
            wmma::fragment<wmma::accumulator, 16, 16, 16, __half> hf;
#pragma unroll
            for (int t = 0; t < hf.num_elements; t++)
                hf.x[t] = __float2half(acc[i][j].x[t]);
            wmma::store_matrix_sync(C + (size_t)r * N + col0 + wn * 32 + j * 16,
                                    hf, N, wmma::mem_row_major);
        }
    }
}

// ------------------------- CSR SpMM (fp16, no atomics) ----------------------
// d=256 split into two column-half passes (keeps gather plane L2-resident).
// One warp per node; lane holds cols [HALF*128 + 4*lane, +4).
template <int HALF>
__global__ void spmm128h(const __half* __restrict__ H, const int* __restrict__ rowptr,
                         const int2* __restrict__ edge, const float* __restrict__ bias,
                         __half* __restrict__ out) {
    int node = (blockIdx.x * blockDim.x + threadIdx.x) >> 5;
    int lane = threadIdx.x & 31;
    if (node >= NN) return;
    int beg = rowptr[node], end = rowptr[node + 1];
    const int col = HALF * 128 + lane * 4;
    float a0 = 0.f, a1 = 0.f, a2 = 0.f, a3 = 0.f;
    for (int e = beg; e < end; e++) {
        int2 ed = edge[e];
        float w = __int_as_float(ed.y);
        uint2 v = *(const uint2*)(H + (size_t)ed.x * 256 + col);
        const __half2* h2 = (const __half2*)&v;
        float2 f0 = __half22float2(h2[0]);
        float2 f1 = __half22float2(h2[1]);
        a0 += w * f0.x; a1 += w * f0.y;
        a2 += w * f1.x; a3 += w * f1.y;
    }
    uint2 o;
    __half2* o2 = (__half2*)&o;
    o2[0] = __floats2half2_rn(fmaxf(a0 + bias[col + 0], 0.f),
                              fmaxf(a1 + bias[col + 1], 0.f));
    o2[1] = __floats2half2_rn(fmaxf(a2 + bias[col + 2], 0.f),
                              fmaxf(a3 + bias[col + 3], 0.f));
    *(uint2*)(out + (size_t)node * 256 + col) = o;
}

// d=64: one warp per node; lane holds cols [2*lane, 2*lane+1].
// MODE 0: out(fp16) = acc + bias.  MODE 1: out(fp32) = log_softmax(acc + bias).
template <int MODE>
__global__ void spmm64h(const __half* __restrict__ H, const int* __restrict__ rowptr,
                        const int2* __restrict__ edge, const float* __restrict__ bias,
                        void* __restrict__ outv) {
    int node = (blockIdx.x * blockDim.x + threadIdx.x) >> 5;
    int lane = threadIdx.x & 31;
    if (node >= NN) return;
    int beg = rowptr[node], end = rowptr[node + 1];
    float ax = 0.f, ay = 0.f;
    int e = beg;
    for (; e + 1 < end; e += 2) {
        int2 e0 = edge[e], e1 = edge[e + 1];
        float w0 = __int_as_float(e0.y), w1 = __int_as_float(e1.y);
        float2 u = __half22float2(*(const __half2*)(H + (size_t)e0.x * 64 + lane * 2));
        float2 v = __half22float2(*(const __half2*)(H + (size_t)e1.x * 64 + lane * 2));
        ax += u.x * w0 + v.x * w1;
        ay += u.y * w0 + v.y * w1;
    }
    if (e < end) {
        int2 e0 = edge[e];
        float w0 = __int_as_float(e0.y);
        float2 u = __half22float2(*(const __half2*)(H + (size_t)e0.x * 64 + lane * 2));
        ax += u.x * w0;
        ay += u.y * w0;
    }
    ax += bias[lane * 2];
    ay += bias[lane * 2 + 1];
    if (MODE == 0) {
        ((__half2*)outv)[(size_t)node * 32 + lane] = __floats2half2_rn(ax, ay);
    } else {
        float m = fmaxf(ax, ay);
#pragma unroll
        for (int o = 16; o; o >>= 1) m = fmaxf(m, __shfl_xor_sync(0xFFFFFFFFu, m, o));
        float s = __expf(ax - m) + __expf(ay - m);
#pragma unroll
        for (int o = 16; o; o >>= 1) s += __shfl_xor_sync(0xFFFFFFFFu, s, o);
        float lg = m + logf(s);
        ((float2*)outv)[(size_t)node * 32 + lane] = make_float2(ax - lg, ay - lg);
    }
}

// ---------------------------------------------------------------------------
extern "C" void kernel_launch(void* const* d_in, const int* in_sizes, int n_in,
                              void* d_out, int out_size) {
    const float* x   = (const float*)d_in[0];
    const int*   src = (const int*)d_in[1];
    const int*   dst = (const int*)d_in[2];
    const float* ew  = (const float*)d_in[3];
    const float* W1  = (const float*)d_in[4];
    const float* b1  = (const float*)d_in[5];
    const float* W2  = (const float*)d_in[6];
    const float* b2  = (const float*)d_in[7];
    const float* W3  = (const float*)d_in[8];
    const float* r   = (const float*)d_in[9];

    __half *xh, *t0h, *h1h, *t1h, *h3h, *w1h, *w2h, *w3h;
    int *deg, *incl, *part, *rowptr, *wofs;
    int2* edge;
    cudaGetSymbolAddress((void**)&xh,  g_Xh);
    cudaGetSymbolAddress((void**)&t0h, g_T0h);
    cudaGetSymbolAddress((void**)&h1h, g_H1h);
    cudaGetSymbolAddress((void**)&t1h, g_T1h);
    cudaGetSymbolAddress((void**)&h3h, g_H3h);
    cudaGetSymbolAddress((void**)&w1h, g_W1h);
    cudaGetSymbolAddress((void**)&w2h, g_W2h);
    cudaGetSymbolAddress((void**)&w3h, g_W3h);
    cudaGetSymbolAddress((void**)&deg, g_deg);
    cudaGetSymbolAddress((void**)&incl, g_incl);
    cudaGetSymbolAddress((void**)&part, g_part);
    cudaGetSymbolAddress((void**)&rowptr, g_rowptr);
    cudaGetSymbolAddress((void**)&wofs, g_wofs);
    cudaGetSymbolAddress((void**)&edge, g_edge);

    const int NB = (NN + 255) / 256;            // 391
    const int WB = (int)(((size_t)NN * 32 + 255) / 256);  // 12500
    const int MB = NPAD / 128;                  // 782

    // ---- phase 1: histogram ∥ all fp32->fp16 conversions ----
    cudaMemsetAsync(deg, 0, NN * sizeof(int));
    fused_front<<<62685, 256>>>(dst, deg, (const float4*)x, xh,
                                (const float4*)W1, w1h,
                                (const float4*)W2, w2h,
                                (const float4*)W3, w3h);

    // ---- phase 2: prefix scan of degrees ----
    scan_block<<<SCAN_B, 1024>>>(deg, incl, part);
    scan_partials<<<1, 32>>>(part);
    scan_finalize<<<NB, 256>>>(deg, incl, part, rowptr, wofs);

    // ---- phase 3: edge scatter ∥ GEMM1 (T0 = x @ W1) ----
    fused_sg<<<14076, 256>>>(src, dst, ew, wofs, edge, xh, w1h, t0h);

    // ---- gc1 aggregate: H1 = relu(spmm(T0) + b1), two column halves ----
    spmm128h<0><<<WB, 256>>>(t0h, rowptr, edge, b1, h1h);
    spmm128h<1><<<WB, 256>>>(t0h, rowptr, edge, b1, h1h);

    // ---- gc2: T1 = H1 @ W2 ; H3 = spmm(T1) + b2 ----
    gemm_h64<<<MB, 256>>>(h1h, w2h, t1h, 256, 64);
    spmm64h<0><<<WB, 256>>>(t1h, rowptr, edge, b2, h3h);

    // ---- gc3: T0(reused, 64-wide) = H3 @ W3 ; out = log_softmax(spmm + r) ----
    gemm_h64<<<MB, 256>>>(h3h, w3h, t0h, 64, 64);
    spmm64h<1><<<WB, 256>>>(t0h, rowptr, edge, r, d_out);
}

// round 8
// speedup vs baseline: 1.0517x; 1.0517x over previous
#include <cuda_runtime.h>
#include <cuda_fp16.h>
#include <mma.h>
#include <cstddef>
#include <cstdint>
using namespace nvcuda;

#define NN 100000
#define EE 3200000
#define NPAD 100096            // 782 * 128 (also mult of 64)
#define SCAN_B 98              // ceil(NN/1024)

// ---------------- scratch (device globals; zero-initialized) ----------------
__device__ __half g_T0h[(size_t)NPAD * 256];  // x@W1 ; reused as [NPAD,64] for gc3
__device__ __half g_H1h[(size_t)NPAD * 256];  // relu(spmm1 + b1)
__device__ __half g_T1h[(size_t)NPAD * 64];   // H1@W2
__device__ __half g_H3h[(size_t)NPAD * 64];   // spmm2 + b2
__device__ __half g_W1h[512 * 256];
__device__ __half g_W2h[256 * 64];
__device__ __half g_W3h[64 * 64];
__device__ int    g_deg[NN];
__device__ int    g_incl[SCAN_B * 1024];
__device__ int    g_part[SCAN_B + 1];
__device__ int    g_rowptr[NN + 1];
__device__ int    g_wofs[NN];
__device__ int2   g_edge[EE];                 // {src, weight-bits}

// ------------------------------ helpers ------------------------------------
__device__ __forceinline__ void cp16(void* s, const void* g) {
    uint32_t sa = (uint32_t)__cvta_generic_to_shared(s);
    asm volatile("cp.async.cg.shared.global [%0], [%1], 16;" :: "r"(sa), "l"(g));
}
__device__ __forceinline__ void cp_commit() {
    asm volatile("cp.async.commit_group;");
}
template <int P>
__device__ __forceinline__ void cp_wait() {
    asm volatile("cp.async.wait_group %0;" :: "n"(P));
}

__device__ __forceinline__ void f2h_unit(const float4* __restrict__ in,
                                         __half* __restrict__ out, int unit) {
    size_t i = (size_t)unit * 256 + threadIdx.x;
    float4 v = in[i];
    __half2* o = (__half2*)(out + i * 4);
    o[0] = __floats2half2_rn(v.x, v.y);
    o[1] = __floats2half2_rn(v.z, v.w);
}

// ---------------------------------------------------------------------------
// fused_front: edge histogram (CSR phase 1) + weight fp32->fp16 conversions.
// grid = 12648: bx < 12500 -> hist block; else conv unit cid = bx - 12500:
//   [0,128) W1 (128 x 1024 elems), [128,144) W2, [144,148) W3.
// ---------------------------------------------------------------------------
__global__ void fused_front(const int* __restrict__ dst, int* __restrict__ deg,
                            const float4* __restrict__ w1, __half* __restrict__ w1h,
                            const float4* __restrict__ w2, __half* __restrict__ w2h,
                            const float4* __restrict__ w3, __half* __restrict__ w3h) {
    int bx = blockIdx.x;
    if (bx < 12500) {
        int i = bx * 256 + threadIdx.x;
        atomicAdd(&deg[dst[i]], 1);
    } else {
        int cid = bx - 12500;
        if (cid < 128)       f2h_unit(w1, w1h, cid);
        else if (cid < 144)  f2h_unit(w2, w2h, cid - 128);
        else                 f2h_unit(w3, w3h, cid - 144);
    }
}

// ---------------------------- CSR scan kernels ------------------------------
__global__ void scan_block(const int* __restrict__ deg, int* __restrict__ incl,
                           int* __restrict__ part) {
    __shared__ int s[1024];
    int tid = threadIdx.x;
    int i = blockIdx.x * 1024 + tid;
    int v = (i < NN) ? deg[i] : 0;
    s[tid] = v;
    __syncthreads();
#pragma unroll
    for (int o = 1; o < 1024; o <<= 1) {
        int t = (tid >= o) ? s[tid - o] : 0;
        __syncthreads();
        if (tid >= o) s[tid] += t;
        __syncthreads();
    }
    incl[i] = s[tid];
    if (tid == 1023) part[blockIdx.x] = s[1023];
}

__global__ void scan_partials(int* __restrict__ part) {
    if (threadIdx.x == 0) {
        int run = 0;
        for (int i = 0; i < SCAN_B; i++) {
            int t = part[i];
            part[i] = run;
            run += t;
        }
    }
}

__global__ void scan_finalize(const int* __restrict__ deg, const int* __restrict__ incl,
                              const int* __restrict__ part, int* __restrict__ rowptr,
                              int* __restrict__ wofs) {
    int i = blockIdx.x * blockDim.x + threadIdx.x;
    if (i < NN) {
        int excl = incl[i] - deg[i] + part[i >> 10];
        rowptr[i] = excl;
        wofs[i] = excl;
    }
    if (i == 0) rowptr[NN] = EE;
}

// ---------------------------------------------------------------------------
// fused_sg: edge scatter (CSR phase 3)  ∥  GEMM1 with fp32 A loaded directly.
// GEMM1: C[NPAD,256](fp16) = x[NN,512](fp32, zero-extended) @ W1h[512,256].
// BM=64, BN=256, BK=32; 256 threads = 8 warps (2 in M x 4 in N), warp 32x64.
// A path: guarded LDG.128 fp32 -> cvt fp16 -> STS (reg double-buffered);
// B path: cp.async fp16, smem double-buffered. One __syncthreads per k-step.
// grid = 14076: bx%9==0 -> gemm tile gid=bx/9 (<1564); else scatter unit.
// ---------------------------------------------------------------------------
#define SA1 40     // As row stride (halfs); 80B = 5*16B
#define SB1 264    // Bs row stride (halfs); 528B = 33*16B
__global__ void __launch_bounds__(256)
fused_sg(const int* __restrict__ src, const int* __restrict__ dst,
         const float* __restrict__ w, int* __restrict__ wofs, int2* __restrict__ edge,
         const float* __restrict__ X, const __half* __restrict__ B,
         __half* __restrict__ C) {
    __shared__ __half As[2][64 * SA1];
    __shared__ __half Bs[2][32 * SB1];

    int bx = blockIdx.x;
    if (bx % 9 != 0) {
        int sid = (bx / 9) * 8 + (bx % 9) - 1;
        if (sid < 12500) {
            int i = sid * 256 + threadIdx.x;
            int pos = atomicAdd(&wofs[dst[i]], 1);
            edge[pos] = make_int2(src[i], __float_as_int(w[i]));
        }
        return;
    }
    const int gid = bx / 9;                 // 0..1563
    const int tid = threadIdx.x;
    const int wid = tid >> 5;
    const int wm = wid & 1;                 // 0..1 -> 32-row slab
    const int wn = wid >> 1;                // 0..3 -> 64-col slab
    const int row0 = gid * 64;
    const int K = 512, N = 256;

    // A-load mapping: thread -> row ar (0..63), col (tid&3)*8 .. +8 (2 float4)
    const int ar = tid >> 2;
    const int ac = (tid & 3) * 8;
    const int agr = row0 + ar;
    const bool avalid = agr < NN;
    const float* Arow = X + (size_t)agr * K + ac;

    // B-load mapping: thread -> row br (0..31), cols (tid&7)*32 .. +32 (4 cp16)
    const int br = tid >> 3;
    const int bc = (tid & 7) * 32;
    const __half* Brow = B + (size_t)br * N + bc;

    wmma::fragment<wmma::accumulator, 16, 16, 16, float> acc[2][4];
#pragma unroll
    for (int i = 0; i < 2; i++)
#pragma unroll
        for (int j = 0; j < 4; j++) wmma::fill_fragment(acc[i][j], 0.0f);

    const int KT = K / 32;   // 16

    float4 a_cur0 = make_float4(0.f, 0.f, 0.f, 0.f), a_cur1 = a_cur0;
    if (avalid) {
        a_cur0 = *(const float4*)(Arow + 0);
        a_cur1 = *(const float4*)(Arow + 4);
    }
#pragma unroll
    for (int j = 0; j < 4; j++) cp16(&Bs[0][br * SB1 + bc + j * 8], Brow + j * 8);
    cp_commit();

    for (int kt = 0; kt < KT; kt++) {
        const int buf = kt & 1;
        // prefetch next B
        if (kt + 1 < KT) {
            const __half* Bn = Brow + (size_t)(kt + 1) * 32 * N;
#pragma unroll
            for (int j = 0; j < 4; j++)
                cp16(&Bs[buf ^ 1][br * SB1 + bc + j * 8], Bn + j * 8);
            cp_commit();
        }
        // store current A (fp32 regs -> fp16 smem)
        {
            __half h[8];
            h[0] = __float2half(a_cur0.x); h[1] = __float2half(a_cur0.y);
            h[2] = __float2half(a_cur0.z); h[3] = __float2half(a_cur0.w);
            h[4] = __float2half(a_cur1.x); h[5] = __float2half(a_cur1.y);
            h[6] = __float2half(a_cur1.z); h[7] = __float2half(a_cur1.w);
            *(uint4*)&As[buf][ar * SA1 + ac] = *(uint4*)h;
        }
        // prefetch next A into regs
        float4 a_n0 = make_float4(0.f, 0.f, 0.f, 0.f), a_n1 = a_n0;
        if (kt + 1 < KT && avalid) {
            const float* An = Arow + (kt + 1) * 32;
            a_n0 = *(const float4*)(An + 0);
            a_n1 = *(const float4*)(An + 4);
        }
        if (kt + 1 < KT) cp_wait<1>(); else cp_wait<0>();
        __syncthreads();
#pragma unroll
        for (int kk = 0; kk < 32; kk += 16) {
            wmma::fragment<wmma::matrix_a, 16, 16, 16, __half, wmma::row_major> fa[2];
            wmma::fragment<wmma::matrix_b, 16, 16, 16, __half, wmma::row_major> fb[4];
#pragma unroll
            for (int i = 0; i < 2; i++)
                wmma::load_matrix_sync(fa[i], &As[buf][(wm * 32 + i * 16) * SA1 + kk], SA1);
#pragma unroll
            for (int j = 0; j < 4; j++)
                wmma::load_matrix_sync(fb[j], &Bs[buf][kk * SB1 + wn * 64 + j * 16], SB1);
#pragma unroll
            for (int i = 0; i < 2; i++)
#pragma unroll
                for (int j = 0; j < 4; j++)
                    wmma::mma_sync(acc[i][j], fa[i], fb[j], acc[i][j]);
        }
        a_cur0 = a_n0;
        a_cur1 = a_n1;
    }

#pragma unroll
    for (int i = 0; i < 2; i++) {
        int rr = row0 + wm * 32 + i * 16;
#pragma unroll
        for (int j = 0; j < 4; j++) {
            wmma::fragment<wmma::accumulator, 16, 16, 16, __half> hf;
#pragma unroll
            for (int t = 0; t < hf.num_elements; t++)
                hf.x[t] = __float2half(acc[i][j].x[t]);
            wmma::store_matrix_sync(C + (size_t)rr * N + wn * 64 + j * 16,
                                    hf, N, wmma::mem_row_major);
        }
    }
}

// ---------------------------------------------------------------------------
// fp16 wmma GEMM (BN=64) with cp.async double buffering — GEMM2/GEMM3.
// ---------------------------------------------------------------------------
__launch_bounds__(256, 2)
__global__ void gemm_h64(const __half* __restrict__ A, const __half* __restrict__ B,
                         __half* __restrict__ C, int K, int N) {
    constexpr int SA = 40;
    constexpr int SB = 72;
    __shared__ __half As[2][128 * SA];
    __shared__ __half Bs[2][32 * SB];

    const int tid = threadIdx.x;
    const int wid = tid >> 5;
    const int wm = wid & 3;
    const int wn = wid >> 2;
    const int row0 = blockIdx.x * 128;

    const int ar = tid >> 2;
    const int ac = (tid & 3) * 8;

    wmma::fragment<wmma::accumulator, 16, 16, 16, float> acc[2][2];
#pragma unroll
    for (int i = 0; i < 2; i++)
#pragma unroll
        for (int j = 0; j < 2; j++) wmma::fill_fragment(acc[i][j], 0.0f);

    const int KT = K / 32;

    auto issue = [&](int buf, int k0) {
        const __half* Ag = A + (size_t)(row0 + ar) * K + k0 + ac;
        cp16(&As[buf][ar * SA + ac], Ag);
        cp16(&As[buf][(ar + 64) * SA + ac], Ag + (size_t)64 * K);
        int brr = tid >> 3, bcc = (tid & 7) * 8;
        cp16(&Bs[buf][brr * SB + bcc], B + (size_t)(k0 + brr) * N + bcc);
    };

    issue(0, 0);
    cp_commit();

    for (int kt = 0; kt < KT; kt++) {
        int buf = kt & 1;
        if (kt + 1 < KT) {
            issue(buf ^ 1, (kt + 1) * 32);
            cp_commit();
            cp_wait<1>();
        } else {
            cp_wait<0>();
        }
        __syncthreads();
#pragma unroll
        for (int kk = 0; kk < 32; kk += 16) {
            wmma::fragment<wmma::matrix_a, 16, 16, 16, __half, wmma::row_major> fa[2];
            wmma::fragment<wmma::matrix_b, 16, 16, 16, __half, wmma::row_major> fb[2];
#pragma unroll
            for (int i = 0; i < 2; i++)
                wmma::load_matrix_sync(fa[i], &As[buf][(wm * 32 + i * 16) * SA + kk], SA);
#pragma unroll
            for (int j = 0; j < 2; j++)
                wmma::load_matrix_sync(fb[j], &Bs[buf][kk * SB + wn * 32 + j * 16], SB);
#pragma unroll
            for (int i = 0; i < 2; i++)
#pragma unroll
                for (int j = 0; j < 2; j++)
                    wmma::mma_sync(acc[i][j], fa[i], fb[j], acc[i][j]);
        }
        __syncthreads();
    }

#pragma unroll
    for (int i = 0; i < 2; i++) {
        int rr = row0 + wm * 32 + i * 16;
#pragma unroll
        for (int j = 0; j < 2; j++) {
            wmma::fragment<wmma::accumulator, 16, 16, 16, __half> hf;
#pragma unroll
            for (int t = 0; t < hf.num_elements; t++)
                hf.x[t] = __float2half(acc[i][j].x[t]);
            wmma::store_matrix_sync(C + (size_t)rr * N + wn * 32 + j * 16,
                                    hf, N, wmma::mem_row_major);
        }
    }
}

// ------------------------- CSR SpMM (fp16, no atomics) ----------------------
// d=256: one warp per node, lane holds cols [8*lane, 8*lane+8). +bias, relu.
__global__ void spmm256h(const __half* __restrict__ H, const int* __restrict__ rowptr,
                         const int2* __restrict__ edge, const float* __restrict__ bias,
                         __half* __restrict__ out) {
    int node = (blockIdx.x * blockDim.x + threadIdx.x) >> 5;
    int lane = threadIdx.x & 31;
    if (node >= NN) return;
    int beg = rowptr[node], end = rowptr[node + 1];
    float a[8];
#pragma unroll
    for (int k = 0; k < 8; k++) a[k] = 0.f;

    for (int e = beg; e < end; e++) {
        int2 ed = edge[e];
        float w = __int_as_float(ed.y);
        uint4 v = *(const uint4*)(H + (size_t)ed.x * 256 + lane * 8);
        const __half2* h2 = (const __half2*)&v;
#pragma unroll
        for (int k = 0; k < 4; k++) {
            float2 f = __half22float2(h2[k]);
            a[2 * k + 0] += w * f.x;
            a[2 * k + 1] += w * f.y;
        }
    }
    uint4 o;
    __half2* o2 = (__half2*)&o;
#pragma unroll
    for (int k = 0; k < 4; k++) {
        float bx = bias[lane * 8 + 2 * k];
        float by = bias[lane * 8 + 2 * k + 1];
        float vx = fmaxf(a[2 * k] + bx, 0.f);
        float vy = fmaxf(a[2 * k + 1] + by, 0.f);
        o2[k] = __floats2half2_rn(vx, vy);
    }
    *(uint4*)(out + (size_t)node * 256 + lane * 8) = o;
}

// d=64: one warp per node; lane holds cols [2*lane, 2*lane+1].
// MODE 0: out(fp16) = acc + bias.  MODE 1: out(fp32) = log_softmax(acc + bias).
template <int MODE>
__global__ void spmm64h(const __half* __restrict__ H, const int* __restrict__ rowptr,
                        const int2* __restrict__ edge, const float* __restrict__ bias,
                        void* __restrict__ outv) {
    int node = (blockIdx.x * blockDim.x + threadIdx.x) >> 5;
    int lane = threadIdx.x & 31;
    if (node >= NN) return;
    int beg = rowptr[node], end = rowptr[node + 1];
    float ax = 0.f, ay = 0.f;
    int e = beg;
    for (; e + 1 < end; e += 2) {
        int2 e0 = edge[e], e1 = edge[e + 1];
        float w0 = __int_as_float(e0.y), w1 = __int_as_float(e1.y);
        float2 u = __half22float2(*(const __half2*)(H + (size_t)e0.x * 64 + lane * 2));
        float2 v = __half22float2(*(const __half2*)(H + (size_t)e1.x * 64 + lane * 2));
        ax += u.x * w0 + v.x * w1;
        ay += u.y * w0 + v.y * w1;
    }
    if (e < end) {
        int2 e0 = edge[e];
        float w0 = __int_as_float(e0.y);
        float2 u = __half22float2(*(const __half2*)(H + (size_t)e0.x * 64 + lane * 2));
        ax += u.x * w0;
        ay += u.y * w0;
    }
    ax += bias[lane * 2];
    ay += bias[lane * 2 + 1];
    if (MODE == 0) {
        ((__half2*)outv)[(size_t)node * 32 + lane] = __floats2half2_rn(ax, ay);
    } else {
        float m = fmaxf(ax, ay);
#pragma unroll
        for (int o = 16; o; o >>= 1) m = fmaxf(m, __shfl_xor_sync(0xFFFFFFFFu, m, o));
        float s = __expf(ax - m) + __expf(ay - m);
#pragma unroll
        for (int o = 16; o; o >>= 1) s += __shfl_xor_sync(0xFFFFFFFFu, s, o);
        float lg = m + logf(s);
        ((float2*)outv)[(size_t)node * 32 + lane] = make_float2(ax - lg, ay - lg);
    }
}

// ---------------------------------------------------------------------------
extern "C" void kernel_launch(void* const* d_in, const int* in_sizes, int n_in,
                              void* d_out, int out_size) {
    const float* x   = (const float*)d_in[0];
    const int*   src = (const int*)d_in[1];
    const int*   dst = (const int*)d_in[2];
    const float* ew  = (const float*)d_in[3];
    const float* W1  = (const float*)d_in[4];
    const float* b1  = (const float*)d_in[5];
    const float* W2  = (const float*)d_in[6];
    const float* b2  = (const float*)d_in[7];
    const float* W3  = (const float*)d_in[8];
    const float* r   = (const float*)d_in[9];

    __half *t0h, *h1h, *t1h, *h3h, *w1h, *w2h, *w3h;
    int *deg, *incl, *part, *rowptr, *wofs;
    int2* edge;
    cudaGetSymbolAddress((void**)&t0h, g_T0h);
    cudaGetSymbolAddress((void**)&h1h, g_H1h);
    cudaGetSymbolAddress((void**)&t1h, g_T1h);
    cudaGetSymbolAddress((void**)&h3h, g_H3h);
    cudaGetSymbolAddress((void**)&w1h, g_W1h);
    cudaGetSymbolAddress((void**)&w2h, g_W2h);
    cudaGetSymbolAddress((void**)&w3h, g_W3h);
    cudaGetSymbolAddress((void**)&deg, g_deg);
    cudaGetSymbolAddress((void**)&incl, g_incl);
    cudaGetSymbolAddress((void**)&part, g_part);
    cudaGetSymbolAddress((void**)&rowptr, g_rowptr);
    cudaGetSymbolAddress((void**)&wofs, g_wofs);
    cudaGetSymbolAddress((void**)&edge, g_edge);

    const int NB = (NN + 255) / 256;            // 391
    const int WB = (int)(((size_t)NN * 32 + 255) / 256);  // 12500
    const int MB = NPAD / 128;                  // 782

    // ---- phase 1: histogram + weight conversions ----
    cudaMemsetAsync(deg, 0, NN * sizeof(int));
    fused_front<<<12648, 256>>>(dst, deg,
                                (const float4*)W1, w1h,
                                (const float4*)W2, w2h,
                                (const float4*)W3, w3h);

    // ---- phase 2: prefix scan of degrees ----
    scan_block<<<SCAN_B, 1024>>>(deg, incl, part);
    scan_partials<<<1, 32>>>(part);
    scan_finalize<<<NB, 256>>>(deg, incl, part, rowptr, wofs);

    // ---- phase 3: edge scatter ∥ GEMM1 (T0 = x @ W1, fp32 A direct) ----
    fused_sg<<<14076, 256>>>(src, dst, ew, wofs, edge, x, w1h, t0h);

    // ---- gc1 aggregate: H1 = relu(spmm(T0) + b1) ----
    spmm256h<<<WB, 256>>>(t0h, rowptr, edge, b1, h1h);

    // ---- gc2: T1 = H1 @ W2 ; H3 = spmm(T1) + b2 ----
    gemm_h64<<<MB, 256>>>(h1h, w2h, t1h, 256, 64);
    spmm64h<0><<<WB, 256>>>(t1h, rowptr, edge, b2, h3h);

    // ---- gc3: T0(reused, 64-wide) = H3 @ W3 ; out = log_softmax(spmm + r) ----
    gemm_h64<<<MB, 256>>>(h3h, w3h, t0h, 64, 64);
    spmm64h<1><<<WB, 256>>>(t0h, rowptr, edge, r, d_out);
}

// round 9
// speedup vs baseline: 1.0721x; 1.0194x over previous
#include <cuda_runtime.h>
#include <cuda_fp16.h>
#include <cuda_fp8.h>
#include <mma.h>
#include <cstddef>
#include <cstdint>
using namespace nvcuda;

#define NN 100000
#define EE 3200000
#define NPAD 100096            // 1564 * 64
#define SCAN_B 98              // ceil(NN/1024)

// ---------------- scratch (device globals; zero-initialized) ----------------
__device__ unsigned char g_T0q[(size_t)NPAD * 256];  // x@W1 in fp8 e4m3
__device__ __half g_H1h[(size_t)NPAD * 256];  // relu(spmm1 + b1)
__device__ __half g_T1h[(size_t)NPAD * 64];   // H1@W23
__device__ __half g_Sh[(size_t)NPAD * 64];    // adj(T1)
__device__ __half g_W1h[512 * 256];
__device__ __half g_W23h[256 * 64];           // W2@W3 (fp16)
__device__ float  g_c[64];                    // b2@W3
__device__ float  g_zero64[64];               // stays zero
__device__ int    g_deg[NN];
__device__ int    g_incl[SCAN_B * 1024];
__device__ int    g_part[SCAN_B + 1];
__device__ int    g_rowptr[NN + 1];
__device__ int    g_wofs[NN];
__device__ int2   g_edge[EE];                 // {src, weight-bits}

// ------------------------------ helpers ------------------------------------
__device__ __forceinline__ void cp16(void* s, const void* g) {
    uint32_t sa = (uint32_t)__cvta_generic_to_shared(s);
    asm volatile("cp.async.cg.shared.global [%0], [%1], 16;" :: "r"(sa), "l"(g));
}
__device__ __forceinline__ void cp_commit() {
    asm volatile("cp.async.commit_group;");
}
template <int P>
__device__ __forceinline__ void cp_wait() {
    asm volatile("cp.async.wait_group %0;" :: "n"(P));
}

__device__ __forceinline__ void f2h_unit(const float4* __restrict__ in,
                                         __half* __restrict__ out, int unit) {
    size_t i = (size_t)unit * 256 + threadIdx.x;
    float4 v = in[i];
    __half2* o = (__half2*)(out + i * 4);
    o[0] = __floats2half2_rn(v.x, v.y);
    o[1] = __floats2half2_rn(v.z, v.w);
}

// ---------------------------------------------------------------------------
// fused_front: edge histogram + W1 conversion + W23 = W2@W3 + c = b2@W3.
// grid = 12693: [0,12500) hist; [12500,12628) W1 conv; [12628,12692) W23;
// 12692: c.
// ---------------------------------------------------------------------------
__global__ void fused_front(const int* __restrict__ dst, int* __restrict__ deg,
                            const float4* __restrict__ w1, __half* __restrict__ w1h,
                            const float* __restrict__ W2, const float* __restrict__ W3,
                            const float* __restrict__ b2,
                            __half* __restrict__ w23h, float* __restrict__ c) {
    int bx = blockIdx.x;
    if (bx < 12500) {
        int i = bx * 256 + threadIdx.x;
        atomicAdd(&deg[dst[i]], 1);
    } else if (bx < 12628) {
        f2h_unit(w1, w1h, bx - 12500);
    } else if (bx < 12692) {
        int idx = (bx - 12628) * 256 + threadIdx.x;  // 0..16383
        int row = idx >> 6, col = idx & 63;
        float s = 0.f;
#pragma unroll 8
        for (int k = 0; k < 64; k++) s += W2[row * 64 + k] * W3[k * 64 + col];
        w23h[idx] = __float2half(s);
    } else {
        if (threadIdx.x < 64) {
            int j = threadIdx.x;
            float s = 0.f;
#pragma unroll 8
            for (int k = 0; k < 64; k++) s += b2[k] * W3[k * 64 + j];
            c[j] = s;
        }
    }
}

// ---------------------------- CSR scan kernels ------------------------------
__global__ void scan_block(const int* __restrict__ deg, int* __restrict__ incl,
                           int* __restrict__ part) {
    __shared__ int s[1024];
    int tid = threadIdx.x;
    int i = blockIdx.x * 1024 + tid;
    int v = (i < NN) ? deg[i] : 0;
    s[tid] = v;
    __syncthreads();
#pragma unroll
    for (int o = 1; o < 1024; o <<= 1) {
        int t = (tid >= o) ? s[tid - o] : 0;
        __syncthreads();
        if (tid >= o) s[tid] += t;
        __syncthreads();
    }
    incl[i] = s[tid];
    if (tid == 1023) part[blockIdx.x] = s[1023];
}

__global__ void scan_partials(int* __restrict__ part) {
    if (threadIdx.x == 0) {
        int run = 0;
        for (int i = 0; i < SCAN_B; i++) {
            int t = part[i];
            part[i] = run;
            run += t;
        }
    }
}

__global__ void scan_finalize(const int* __restrict__ deg, const int* __restrict__ incl,
                              const int* __restrict__ part, int* __restrict__ rowptr,
                              int* __restrict__ wofs) {
    int i = blockIdx.x * blockDim.x + threadIdx.x;
    if (i < NN) {
        int excl = incl[i] - deg[i] + part[i >> 10];
        rowptr[i] = excl;
        wofs[i] = excl;
    }
    if (i == 0) rowptr[NN] = EE;
}

// ---------------------------------------------------------------------------
// fused_sg: edge scatter ∥ GEMM1 (fp32 A direct -> fp8 e4m3 output).
// GEMM1: T0q[NPAD,256](fp8) = x[NN,512](fp32, zero-extended) @ W1h[512,256].
// BM=64, BN=256, BK=32; 256 threads = 8 warps (2 M x 4 N), warp 32x64.
// grid = 14076: bx%9==0 -> gemm tile gid=bx/9 (<1564); else scatter unit.
// ---------------------------------------------------------------------------
#define SA1 40     // As row stride (halfs)
#define SB1 264    // Bs row stride (halfs); also epilogue staging stride
__global__ void __launch_bounds__(256)
fused_sg(const int* __restrict__ src, const int* __restrict__ dst,
         const float* __restrict__ w, int* __restrict__ wofs, int2* __restrict__ edge,
         const float* __restrict__ X, const __half* __restrict__ B,
         unsigned char* __restrict__ C8) {
    __shared__ __half As[2][64 * SA1];
    __shared__ __half Bs[2][32 * SB1];   // 16896 halfs; reused as 64x264 staging

    int bx = blockIdx.x;
    if (bx % 9 != 0) {
        int sid = (bx / 9) * 8 + (bx % 9) - 1;
        if (sid < 12500) {
            int i = sid * 256 + threadIdx.x;
            int pos = atomicAdd(&wofs[dst[i]], 1);
            edge[pos] = make_int2(src[i], __float_as_int(w[i]));
        }
        return;
    }
    const int gid = bx / 9;                 // 0..1563
    const int tid = threadIdx.x;
    const int wid = tid >> 5;
    const int wm = wid & 1;
    const int wn = wid >> 1;
    const int row0 = gid * 64;
    const int K = 512, N = 256;

    const int ar = tid >> 2;
    const int ac = (tid & 3) * 8;
    const int agr = row0 + ar;
    const bool avalid = agr < NN;
    const float* Arow = X + (size_t)agr * K + ac;

    const int br = tid >> 3;
    const int bc = (tid & 7) * 32;
    const __half* Brow = B + (size_t)br * N + bc;

    wmma::fragment<wmma::accumulator, 16, 16, 16, float> acc[2][4];
#pragma unroll
    for (int i = 0; i < 2; i++)
#pragma unroll
        for (int j = 0; j < 4; j++) wmma::fill_fragment(acc[i][j], 0.0f);

    const int KT = K / 32;   // 16

    float4 a_cur0 = make_float4(0.f, 0.f, 0.f, 0.f), a_cur1 = a_cur0;
    if (avalid) {
        a_cur0 = *(const float4*)(Arow + 0);
        a_cur1 = *(const float4*)(Arow + 4);
    }
#pragma unroll
    for (int j = 0; j < 4; j++) cp16(&Bs[0][br * SB1 + bc + j * 8], Brow + j * 8);
    cp_commit();

    for (int kt = 0; kt < KT; kt++) {
        const int buf = kt & 1;
        if (kt + 1 < KT) {
            const __half* Bn = Brow + (size_t)(kt + 1) * 32 * N;
#pragma unroll
            for (int j = 0; j < 4; j++)
                cp16(&Bs[buf ^ 1][br * SB1 + bc + j * 8], Bn + j * 8);
            cp_commit();
        }
        {
            __half h[8];
            h[0] = __float2half(a_cur0.x); h[1] = __float2half(a_cur0.y);
            h[2] = __float2half(a_cur0.z); h[3] = __float2half(a_cur0.w);
            h[4] = __float2half(a_cur1.x); h[5] = __float2half(a_cur1.y);
            h[6] = __float2half(a_cur1.z); h[7] = __float2half(a_cur1.w);
            *(uint4*)&As[buf][ar * SA1 + ac] = *(uint4*)h;
        }
        float4 a_n0 = make_float4(0.f, 0.f, 0.f, 0.f), a_n1 = a_n0;
        if (kt + 1 < KT && avalid) {
            const float* An = Arow + (kt + 1) * 32;
            a_n0 = *(const float4*)(An + 0);
            a_n1 = *(const float4*)(An + 4);
        }
        if (kt + 1 < KT) cp_wait<1>(); else cp_wait<0>();
        __syncthreads();
#pragma unroll
        for (int kk = 0; kk < 32; kk += 16) {
            wmma::fragment<wmma::matrix_a, 16, 16, 16, __half, wmma::row_major> fa[2];
            wmma::fragment<wmma::matrix_b, 16, 16, 16, __half, wmma::row_major> fb[4];
#pragma unroll
            for (int i = 0; i < 2; i++)
                wmma::load_matrix_sync(fa[i], &As[buf][(wm * 32 + i * 16) * SA1 + kk], SA1);
#pragma unroll
            for (int j = 0; j < 4; j++)
                wmma::load_matrix_sync(fb[j], &Bs[buf][kk * SB1 + wn * 64 + j * 16], SB1);
#pragma unroll
            for (int i = 0; i < 2; i++)
#pragma unroll
                for (int j = 0; j < 4; j++)
                    wmma::mma_sync(acc[i][j], fa[i], fb[j], acc[i][j]);
        }
        a_cur0 = a_n0;
        a_cur1 = a_n1;
        __syncthreads();
    }

    // epilogue: stage fp16 tile in smem (reuse Bs), then convert to fp8.
    __half* stage = &Bs[0][0];   // 64 x 264 halfs
#pragma unroll
    for (int i = 0; i < 2; i++) {
#pragma unroll
        for (int j = 0; j < 4; j++) {
            wmma::fragment<wmma::accumulator, 16, 16, 16, __half> hf;
#pragma unroll
            for (int t = 0; t < hf.num_elements; t++)
                hf.x[t] = __float2half(acc[i][j].x[t]);
            wmma::store_matrix_sync(stage + (wm * 32 + i * 16) * SB1 + wn * 64 + j * 16,
                                    hf, SB1, wmma::mem_row_major);
        }
    }
    __syncthreads();
    {
        int row = tid >> 2;
        int cb = (tid & 3) * 64;
        const __half2* sp = (const __half2*)(stage + row * SB1 + cb);
        unsigned short q[32];
#pragma unroll
        for (int k = 0; k < 32; k++) {
            __half2 h2 = sp[k];
            q[k] = __nv_cvt_halfraw2_to_fp8x2(*(__half2_raw*)&h2,
                                              __NV_SATFINITE, __NV_E4M3);
        }
        uint4* gp = (uint4*)(C8 + (size_t)(row0 + row) * 256 + cb);
#pragma unroll
        for (int k = 0; k < 4; k++) gp[k] = ((uint4*)q)[k];
    }
}

// ---------------------------------------------------------------------------
// fp16 wmma GEMM (BN=64) with cp.async double buffering — GEMM2.
// ---------------------------------------------------------------------------
__launch_bounds__(256, 2)
__global__ void gemm_h64(const __half* __restrict__ A, const __half* __restrict__ B,
                         __half* __restrict__ C, int K, int N) {
    constexpr int SA = 40;
    constexpr int SB = 72;
    __shared__ __half As[2][128 * SA];
    __shared__ __half Bs[2][32 * SB];

    const int tid = threadIdx.x;
    const int wid = tid >> 5;
    const int wm = wid & 3;
    const int wn = wid >> 2;
    const int row0 = blockIdx.x * 128;

    const int ar = tid >> 2;
    const int ac = (tid & 3) * 8;

    wmma::fragment<wmma::accumulator, 16, 16, 16, float> acc[2][2];
#pragma unroll
    for (int i = 0; i < 2; i++)
#pragma unroll
        for (int j = 0; j < 2; j++) wmma::fill_fragment(acc[i][j], 0.0f);

    const int KT = K / 32;

    auto issue = [&](int buf, int k0) {
        const __half* Ag = A + (size_t)(row0 + ar) * K + k0 + ac;
        cp16(&As[buf][ar * SA + ac], Ag);
        cp16(&As[buf][(ar + 64) * SA + ac], Ag + (size_t)64 * K);
        int brr = tid >> 3, bcc = (tid & 7) * 8;
        cp16(&Bs[buf][brr * SB + bcc], B + (size_t)(k0 + brr) * N + bcc);
    };

    issue(0, 0);
    cp_commit();

    for (int kt = 0; kt < KT; kt++) {
        int buf = kt & 1;
        if (kt + 1 < KT) {
            issue(buf ^ 1, (kt + 1) * 32);
            cp_commit();
            cp_wait<1>();
        } else {
            cp_wait<0>();
        }
        __syncthreads();
#pragma unroll
        for (int kk = 0; kk < 32; kk += 16) {
            wmma::fragment<wmma::matrix_a, 16, 16, 16, __half, wmma::row_major> fa[2];
            wmma::fragment<wmma::matrix_b, 16, 16, 16, __half, wmma::row_major> fb[2];
#pragma unroll
            for (int i = 0; i < 2; i++)
                wmma::load_matrix_sync(fa[i], &As[buf][(wm * 32 + i * 16) * SA + kk], SA);
#pragma unroll
            for (int j = 0; j < 2; j++)
                wmma::load_matrix_sync(fb[j], &Bs[buf][kk * SB + wn * 32 + j * 16], SB);
#pragma unroll
            for (int i = 0; i < 2; i++)
#pragma unroll
                for (int j = 0; j < 2; j++)
                    wmma::mma_sync(acc[i][j], fa[i], fb[j], acc[i][j]);
        }
        __syncthreads();
    }

#pragma unroll
    for (int i = 0; i < 2; i++) {
        int rr = row0 + wm * 32 + i * 16;
#pragma unroll
        for (int j = 0; j < 2; j++) {
            wmma::fragment<wmma::accumulator, 16, 16, 16, __half> hf;
#pragma unroll
            for (int t = 0; t < hf.num_elements; t++)
                hf.x[t] = __float2half(acc[i][j].x[t]);
            wmma::store_matrix_sync(C + (size_t)rr * N + wn * 32 + j * 16,
                                    hf, N, wmma::mem_row_major);
        }
    }
}

// ------------------------- CSR SpMM (no atomics) ----------------------------
// d=256 fp8 gather: one warp per node, lane holds cols [8*lane, +8).
// out(fp16) = relu(acc + b1).
__global__ void spmm256q(const unsigned char* __restrict__ Q,
                         const int* __restrict__ rowptr,
                         const int2* __restrict__ edge, const float* __restrict__ bias,
                         __half* __restrict__ out) {
    int node = (blockIdx.x * blockDim.x + threadIdx.x) >> 5;
    int lane = threadIdx.x & 31;
    if (node >= NN) return;
    int beg = rowptr[node], end = rowptr[node + 1];
    float a[8];
#pragma unroll
    for (int k = 0; k < 8; k++) a[k] = 0.f;

    int e = beg;
    for (; e + 1 < end; e += 2) {
        int2 e0 = edge[e], e1 = edge[e + 1];
        float w0 = __int_as_float(e0.y), w1 = __int_as_float(e1.y);
        uint2 v0 = *(const uint2*)(Q + (size_t)e0.x * 256 + lane * 8);
        uint2 v1 = *(const uint2*)(Q + (size_t)e1.x * 256 + lane * 8);
        const unsigned short* p0 = (const unsigned short*)&v0;
        const unsigned short* p1 = (const unsigned short*)&v1;
#pragma unroll
        for (int k = 0; k < 4; k++) {
            __half2_raw h0 = __nv_cvt_fp8x2_to_halfraw2(p0[k], __NV_E4M3);
            __half2_raw h1 = __nv_cvt_fp8x2_to_halfraw2(p1[k], __NV_E4M3);
            float2 f0 = __half22float2(*(__half2*)&h0);
            float2 f1 = __half22float2(*(__half2*)&h1);
            a[2 * k + 0] += w0 * f0.x + w1 * f1.x;
            a[2 * k + 1] += w0 * f0.y + w1 * f1.y;
        }
    }
    if (e < end) {
        int2 e0 = edge[e];
        float w0 = __int_as_float(e0.y);
        uint2 v0 = *(const uint2*)(Q + (size_t)e0.x * 256 + lane * 8);
        const unsigned short* p0 = (const unsigned short*)&v0;
#pragma unroll
        for (int k = 0; k < 4; k++) {
            __half2_raw h0 = __nv_cvt_fp8x2_to_halfraw2(p0[k], __NV_E4M3);
            float2 f0 = __half22float2(*(__half2*)&h0);
            a[2 * k + 0] += w0 * f0.x;
            a[2 * k + 1] += w0 * f0.y;
        }
    }
    uint4 o;
    __half2* o2 = (__half2*)&o;
#pragma unroll
    for (int k = 0; k < 4; k++) {
        float bx = bias[lane * 8 + 2 * k];
        float by = bias[lane * 8 + 2 * k + 1];
        o2[k] = __floats2half2_rn(fmaxf(a[2 * k] + bx, 0.f),
                                  fmaxf(a[2 * k + 1] + by, 0.f));
    }
    *(uint4*)(out + (size_t)node * 256 + lane * 8) = o;
}

// d=64 fp16: one warp per node; lane holds cols [2*lane, 2*lane+1].
// out(fp16) = acc + bias (bias may be the zero vector).
__global__ void spmm64h(const __half* __restrict__ H, const int* __restrict__ rowptr,
                        const int2* __restrict__ edge, const float* __restrict__ bias,
                        __half2* __restrict__ out) {
    int node = (blockIdx.x * blockDim.x + threadIdx.x) >> 5;
    int lane = threadIdx.x & 31;
    if (node >= NN) return;
    int beg = rowptr[node], end = rowptr[node + 1];
    float ax = 0.f, ay = 0.f;
    int e = beg;
    for (; e + 1 < end; e += 2) {
        int2 e0 = edge[e], e1 = edge[e + 1];
        float w0 = __int_as_float(e0.y), w1 = __int_as_float(e1.y);
        float2 u = __half22float2(*(const __half2*)(H + (size_t)e0.x * 64 + lane * 2));
        float2 v = __half22float2(*(const __half2*)(H + (size_t)e1.x * 64 + lane * 2));
        ax += u.x * w0 + v.x * w1;
        ay += u.y * w0 + v.y * w1;
    }
    if (e < end) {
        int2 e0 = edge[e];
        float w0 = __int_as_float(e0.y);
        float2 u = __half22float2(*(const __half2*)(H + (size_t)e0.x * 64 + lane * 2));
        ax += u.x * w0;
        ay += u.y * w0;
    }
    ax += bias[lane * 2];
    ay += bias[lane * 2 + 1];
    out[(size_t)node * 32 + lane] = __floats2half2_rn(ax, ay);
}

// Final pass: T2 = adj S + degw*c + r; out(fp32) = log_softmax(T2).
// degw (sum of incoming edge weights) accumulated in-loop.
__global__ void spmm64_final(const __half* __restrict__ H, const int* __restrict__ rowptr,
                             const int2* __restrict__ edge, const float* __restrict__ c,
                             const float* __restrict__ r, float2* __restrict__ out) {
    int node = (blockIdx.x * blockDim.x + threadIdx.x) >> 5;
    int lane = threadIdx.x & 31;
    if (node >= NN) return;
    int beg = rowptr[node], end = rowptr[node + 1];
    float ax = 0.f, ay = 0.f, dw = 0.f;
    int e = beg;
    for (; e + 1 < end; e += 2) {
        int2 e0 = edge[e], e1 = edge[e + 1];
        float w0 = __int_as_float(e0.y), w1 = __int_as_float(e1.y);
        float2 u = __half22float2(*(const __half2*)(H + (size_t)e0.x * 64 + lane * 2));
        float2 v = __half22float2(*(const __half2*)(H + (size_t)e1.x * 64 + lane * 2));
        ax += u.x * w0 + v.x * w1;
        ay += u.y * w0 + v.y * w1;
        dw += w0 + w1;
    }
    if (e < end) {
        int2 e0 = edge[e];
        float w0 = __int_as_float(e0.y);
        float2 u = __half22float2(*(const __half2*)(H + (size_t)e0.x * 64 + lane * 2));
        ax += u.x * w0;
        ay += u.y * w0;
        dw += w0;
    }
    ax += dw * c[lane * 2 + 0] + r[lane * 2 + 0];
    ay += dw * c[lane * 2 + 1] + r[lane * 2 + 1];
    float m = fmaxf(ax, ay);
#pragma unroll
    for (int o = 16; o; o >>= 1) m = fmaxf(m, __shfl_xor_sync(0xFFFFFFFFu, m, o));
    float s = __expf(ax - m) + __expf(ay - m);
#pragma unroll
    for (int o = 16; o; o >>= 1) s += __shfl_xor_sync(0xFFFFFFFFu, s, o);
    float lg = m + logf(s);
    out[(size_t)node * 32 + lane] = make_float2(ax - lg, ay - lg);
}

// ---------------------------------------------------------------------------
extern "C" void kernel_launch(void* const* d_in, const int* in_sizes, int n_in,
                              void* d_out, int out_size) {
    const float* x   = (const float*)d_in[0];
    const int*   src = (const int*)d_in[1];
    const int*   dst = (const int*)d_in[2];
    const float* ew  = (const float*)d_in[3];
    const float* W1  = (const float*)d_in[4];
    const float* b1  = (const float*)d_in[5];
    const float* W2  = (const float*)d_in[6];
    const float* b2  = (const float*)d_in[7];
    const float* W3  = (const float*)d_in[8];
    const float* r   = (const float*)d_in[9];

    unsigned char* t0q;
    __half *h1h, *t1h, *sh, *w1h, *w23h;
    float *cvec, *zero64;
    int *deg, *incl, *part, *rowptr, *wofs;
    int2* edge;
    cudaGetSymbolAddress((void**)&t0q, g_T0q);
    cudaGetSymbolAddress((void**)&h1h, g_H1h);
    cudaGetSymbolAddress((void**)&t1h, g_T1h);
    cudaGetSymbolAddress((void**)&sh,  g_Sh);
    cudaGetSymbolAddress((void**)&w1h, g_W1h);
    cudaGetSymbolAddress((void**)&w23h, g_W23h);
    cudaGetSymbolAddress((void**)&cvec, g_c);
    cudaGetSymbolAddress((void**)&zero64, g_zero64);
    cudaGetSymbolAddress((void**)&deg, g_deg);
    cudaGetSymbolAddress((void**)&incl, g_incl);
    cudaGetSymbolAddress((void**)&part, g_part);
    cudaGetSymbolAddress((void**)&rowptr, g_rowptr);
    cudaGetSymbolAddress((void**)&wofs, g_wofs);
    cudaGetSymbolAddress((void**)&edge, g_edge);

    const int NB = (NN + 255) / 256;            // 391
    const int WB = (int)(((size_t)NN * 32 + 255) / 256);  // 12500
    const int MB = NPAD / 128;                  // 782

    // ---- phase 1: histogram + W1 conv + W23 + c ----
    cudaMemsetAsync(deg, 0, NN * sizeof(int));
    fused_front<<<12693, 256>>>(dst, deg, (const float4*)W1, w1h, W2, W3, b2,
                                w23h, cvec);

    // ---- phase 2: prefix scan of degrees ----
    scan_block<<<SCAN_B, 1024>>>(deg, incl, part);
    scan_partials<<<1, 32>>>(part);
    scan_finalize<<<NB, 256>>>(deg, incl, part, rowptr, wofs);

    // ---- phase 3: edge scatter ∥ GEMM1 (T0q = fp8(x @ W1)) ----
    fused_sg<<<14076, 256>>>(src, dst, ew, wofs, edge, x, w1h, t0q);

    // ---- gc1 aggregate: H1 = relu(spmm(T0q) + b1) ----
    spmm256q<<<WB, 256>>>(t0q, rowptr, edge, b1, h1h);

    // ---- gc2+gc3 fused weights: T1 = H1 @ (W2@W3) ----
    gemm_h64<<<MB, 256>>>(h1h, w23h, t1h, 256, 64);

    // ---- S = adj T1 (no bias) ----
    spmm64h<<<WB, 256>>>(t1h, rowptr, edge, zero64, (__half2*)sh);

    // ---- out = log_softmax(adj S + degw*c + r) ----
    spmm64_final<<<WB, 256>>>(sh, rowptr, edge, cvec, r, (float2*)d_out);
}

// round 10
// speedup vs baseline: 1.2055x; 1.1244x over previous
#include <cuda_runtime.h>
#include <cuda_fp16.h>
#include <cuda_fp8.h>
#include <mma.h>
#include <cstddef>
#include <cstdint>
using namespace nvcuda;

#define NN 100000
#define EE 3200000
#define NPAD 100096            // 1564 * 64
#define SCAN_B 98              // ceil(NN/1024)

// ---------------- scratch (device globals; zero-initialized) ----------------
__device__ unsigned char g_T0q[(size_t)NPAD * 256];  // x@W1 in fp8 e4m3
__device__ __half g_H1h[(size_t)NPAD * 256];  // relu(spmm1 + b1), fp16
__device__ unsigned char g_T1q[(size_t)NPAD * 64];   // H1@W23, fp8
__device__ unsigned char g_Sq[(size_t)NPAD * 64];    // adj(T1), fp8
__device__ __half g_W1h[512 * 256];
__device__ __half g_W23h[256 * 64];           // W2@W3 (fp16)
__device__ float  g_c[64];                    // b2@W3
__device__ int    g_deg[NN];
__device__ int    g_incl[SCAN_B * 1024];
__device__ int    g_part[SCAN_B];
__device__ int    g_rowptr[NN + 1];
__device__ int    g_wofs[NN];
__device__ int2   g_edge[EE];                 // {src, weight-bits}

// ------------------------------ helpers ------------------------------------
__device__ __forceinline__ void cp16(void* s, const void* g) {
    uint32_t sa = (uint32_t)__cvta_generic_to_shared(s);
    asm volatile("cp.async.cg.shared.global [%0], [%1], 16;" :: "r"(sa), "l"(g));
}
__device__ __forceinline__ void cp_commit() {
    asm volatile("cp.async.commit_group;");
}
template <int P>
__device__ __forceinline__ void cp_wait() {
    asm volatile("cp.async.wait_group %0;" :: "n"(P));
}
__device__ __forceinline__ float2 fp8x2_to_f2(unsigned short q) {
    __half2_raw h = __nv_cvt_fp8x2_to_halfraw2(q, __NV_E4M3);
    return __half22float2(*(__half2*)&h);
}
__device__ __forceinline__ unsigned short f2_to_fp8x2(float x, float y) {
    __half2 h = __floats2half2_rn(x, y);
    return __nv_cvt_halfraw2_to_fp8x2(*(__half2_raw*)&h, __NV_SATFINITE, __NV_E4M3);
}

__device__ __forceinline__ void f2h_unit(const float4* __restrict__ in,
                                         __half* __restrict__ out, int unit) {
    size_t i = (size_t)unit * 256 + threadIdx.x;
    float4 v = in[i];
    __half2* o = (__half2*)(out + i * 4);
    o[0] = __floats2half2_rn(v.x, v.y);
    o[1] = __floats2half2_rn(v.z, v.w);
}

// ---------------------------------------------------------------------------
// fused_front: edge histogram + W1 conversion + W23 = W2@W3 + c = b2@W3.
// grid = 12693: [0,12500) hist; [12500,12628) W1 conv; [12628,12692) W23;
// 12692: c.
// ---------------------------------------------------------------------------
__global__ void fused_front(const int* __restrict__ dst, int* __restrict__ deg,
                            const float4* __restrict__ w1, __half* __restrict__ w1h,
                            const float* __restrict__ W2, const float* __restrict__ W3,
                            const float* __restrict__ b2,
                            __half* __restrict__ w23h, float* __restrict__ c) {
    int bx = blockIdx.x;
    if (bx < 12500) {
        int i = bx * 256 + threadIdx.x;
        atomicAdd(&deg[dst[i]], 1);
    } else if (bx < 12628) {
        f2h_unit(w1, w1h, bx - 12500);
    } else if (bx < 12692) {
        int idx = (bx - 12628) * 256 + threadIdx.x;  // 0..16383
        int row = idx >> 6, col = idx & 63;
        float s = 0.f;
#pragma unroll 8
        for (int k = 0; k < 64; k++) s += W2[row * 64 + k] * W3[k * 64 + col];
        w23h[idx] = __float2half(s);
    } else {
        if (threadIdx.x < 64) {
            int j = threadIdx.x;
            float s = 0.f;
#pragma unroll 8
            for (int k = 0; k < 64; k++) s += b2[k] * W3[k * 64 + j];
            c[j] = s;
        }
    }
}

// ---------------------------- CSR scan kernels ------------------------------
__global__ void scan_block(const int* __restrict__ deg, int* __restrict__ incl,
                           int* __restrict__ part) {
    __shared__ int s[1024];
    int tid = threadIdx.x;
    int i = blockIdx.x * 1024 + tid;
    int v = (i < NN) ? deg[i] : 0;
    s[tid] = v;
    __syncthreads();
#pragma unroll
    for (int o = 1; o < 1024; o <<= 1) {
        int t = (tid >= o) ? s[tid - o] : 0;
        __syncthreads();
        if (tid >= o) s[tid] += t;
        __syncthreads();
    }
    incl[i] = s[tid];
    if (tid == 1023) part[blockIdx.x] = s[1023];
}

// Merged partial-prefix + finalize: each 256-node block lies inside ONE
// 1024-node scan-block sb = bx>>2; prefix = sum(part[0..sb)).
__global__ void scan_finalize(const int* __restrict__ deg, const int* __restrict__ incl,
                              const int* __restrict__ part, int* __restrict__ rowptr,
                              int* __restrict__ wofs) {
    __shared__ int red[256];
    int tid = threadIdx.x;
    int bx = blockIdx.x;
    int sb = bx >> 2;
    int v = (tid < SCAN_B && tid < sb) ? part[tid] : 0;
    red[tid] = v;
    __syncthreads();
#pragma unroll
    for (int o = 128; o; o >>= 1) {
        if (tid < o) red[tid] += red[tid + o];
        __syncthreads();
    }
    int pref = red[0];
    int i = bx * 256 + tid;
    if (i < NN) {
        int excl = incl[i] - deg[i] + pref;
        rowptr[i] = excl;
        wofs[i] = excl;
    }
    if (i == 0) rowptr[NN] = EE;
}

// ---------------------------------------------------------------------------
// fused_sg: edge scatter ∥ GEMM1 (fp32 A direct -> fp8 e4m3 output).
// GEMM1: T0q[NPAD,256](fp8) = x[NN,512](fp32, zero-extended) @ W1h[512,256].
// BM=64, BN=256, BK=32; 256 threads = 8 warps (2 M x 4 N), warp 32x64.
// grid = 14076: bx%9==0 -> gemm tile gid=bx/9 (<1564); else scatter unit.
// ---------------------------------------------------------------------------
#define SA1 40     // As row stride (halfs)
#define SB1 264    // Bs row stride (halfs); also epilogue staging stride
__global__ void __launch_bounds__(256)
fused_sg(const int* __restrict__ src, const int* __restrict__ dst,
         const float* __restrict__ w, int* __restrict__ wofs, int2* __restrict__ edge,
         const float* __restrict__ X, const __half* __restrict__ B,
         unsigned char* __restrict__ C8) {
    __shared__ __half As[2][64 * SA1];
    __shared__ __half Bs[2][32 * SB1];   // reused as 64x264 epilogue staging

    int bx = blockIdx.x;
    if (bx % 9 != 0) {
        int sid = (bx / 9) * 8 + (bx % 9) - 1;
        if (sid < 12500) {
            int i = sid * 256 + threadIdx.x;
            int pos = atomicAdd(&wofs[dst[i]], 1);
            edge[pos] = make_int2(src[i], __float_as_int(w[i]));
        }
        return;
    }
    const int gid = bx / 9;                 // 0..1563
    const int tid = threadIdx.x;
    const int wid = tid >> 5;
    const int wm = wid & 1;
    const int wn = wid >> 1;
    const int row0 = gid * 64;
    const int K = 512, N = 256;

    const int ar = tid >> 2;
    const int ac = (tid & 3) * 8;
    const int agr = row0 + ar;
    const bool avalid = agr < NN;
    const float* Arow = X + (size_t)agr * K + ac;

    const int br = tid >> 3;
    const int bc = (tid & 7) * 32;
    const __half* Brow = B + (size_t)br * N + bc;

    wmma::fragment<wmma::accumulator, 16, 16, 16, float> acc[2][4];
#pragma unroll
    for (int i = 0; i < 2; i++)
#pragma unroll
        for (int j = 0; j < 4; j++) wmma::fill_fragment(acc[i][j], 0.0f);

    const int KT = K / 32;   // 16

    float4 a_cur0 = make_float4(0.f, 0.f, 0.f, 0.f), a_cur1 = a_cur0;
    if (avalid) {
        a_cur0 = *(const float4*)(Arow + 0);
        a_cur1 = *(const float4*)(Arow + 4);
    }
#pragma unroll
    for (int j = 0; j < 4; j++) cp16(&Bs[0][br * SB1 + bc + j * 8], Brow + j * 8);
    cp_commit();

    for (int kt = 0; kt < KT; kt++) {
        const int buf = kt & 1;
        if (kt + 1 < KT) {
            const __half* Bn = Brow + (size_t)(kt + 1) * 32 * N;
#pragma unroll
            for (int j = 0; j < 4; j++)
                cp16(&Bs[buf ^ 1][br * SB1 + bc + j * 8], Bn + j * 8);
            cp_commit();
        }
        {
            __half h[8];
            h[0] = __float2half(a_cur0.x); h[1] = __float2half(a_cur0.y);
            h[2] = __float2half(a_cur0.z); h[3] = __float2half(a_cur0.w);
            h[4] = __float2half(a_cur1.x); h[5] = __float2half(a_cur1.y);
            h[6] = __float2half(a_cur1.z); h[7] = __float2half(a_cur1.w);
            *(uint4*)&As[buf][ar * SA1 + ac] = *(uint4*)h;
        }
        float4 a_n0 = make_float4(0.f, 0.f, 0.f, 0.f), a_n1 = a_n0;
        if (kt + 1 < KT && avalid) {
            const float* An = Arow + (kt + 1) * 32;
            a_n0 = *(const float4*)(An + 0);
            a_n1 = *(const float4*)(An + 4);
        }
        if (kt + 1 < KT) cp_wait<1>(); else cp_wait<0>();
        __syncthreads();
#pragma unroll
        for (int kk = 0; kk < 32; kk += 16) {
            wmma::fragment<wmma::matrix_a, 16, 16, 16, __half, wmma::row_major> fa[2];
            wmma::fragment<wmma::matrix_b, 16, 16, 16, __half, wmma::row_major> fb[4];
#pragma unroll
            for (int i = 0; i < 2; i++)
                wmma::load_matrix_sync(fa[i], &As[buf][(wm * 32 + i * 16) * SA1 + kk], SA1);
#pragma unroll
            for (int j = 0; j < 4; j++)
                wmma::load_matrix_sync(fb[j], &Bs[buf][kk * SB1 + wn * 64 + j * 16], SB1);
#pragma unroll
            for (int i = 0; i < 2; i++)
#pragma unroll
                for (int j = 0; j < 4; j++)
                    wmma::mma_sync(acc[i][j], fa[i], fb[j], acc[i][j]);
        }
        a_cur0 = a_n0;
        a_cur1 = a_n1;
        __syncthreads();
    }

    // epilogue: stage fp16 tile in smem (reuse Bs), then convert to fp8.
    __half* stage = &Bs[0][0];   // 64 x 264 halfs
#pragma unroll
    for (int i = 0; i < 2; i++) {
#pragma unroll
        for (int j = 0; j < 4; j++) {
            wmma::fragment<wmma::accumulator, 16, 16, 16, __half> hf;
#pragma unroll
            for (int t = 0; t < hf.num_elements; t++)
                hf.x[t] = __float2half(acc[i][j].x[t]);
            wmma::store_matrix_sync(stage + (wm * 32 + i * 16) * SB1 + wn * 64 + j * 16,
                                    hf, SB1, wmma::mem_row_major);
        }
    }
    __syncthreads();
    {
        int row = tid >> 2;
        int cb = (tid & 3) * 64;
        const __half2* sp = (const __half2*)(stage + row * SB1 + cb);
        unsigned short q[32];
#pragma unroll
        for (int k = 0; k < 32; k++) {
            __half2 h2 = sp[k];
            q[k] = __nv_cvt_halfraw2_to_fp8x2(*(__half2_raw*)&h2,
                                              __NV_SATFINITE, __NV_E4M3);
        }
        uint4* gp = (uint4*)(C8 + (size_t)(row0 + row) * 256 + cb);
#pragma unroll
        for (int k = 0; k < 4; k++) gp[k] = ((uint4*)q)[k];
    }
}

// ---------------------------------------------------------------------------
// GEMM2: T1q[NPAD,64](fp8) = H1[NPAD,256](fp16) @ W23h[256,64](fp16).
// BM=128, BN=64, BK=32; fp8 epilogue via smem staging.
// ---------------------------------------------------------------------------
__launch_bounds__(256, 2)
__global__ void gemm_h64q(const __half* __restrict__ A, const __half* __restrict__ B,
                          unsigned char* __restrict__ C8, int K) {
    constexpr int SA = 40;
    constexpr int SB = 72;
    constexpr int N = 64;
    __shared__ __half As[2][128 * SA];     // 10240 halfs; also epilogue staging
    __shared__ __half Bs[2][32 * SB];

    const int tid = threadIdx.x;
    const int wid = tid >> 5;
    const int wm = wid & 3;
    const int wn = wid >> 2;
    const int row0 = blockIdx.x * 128;

    const int ar = tid >> 2;
    const int ac = (tid & 3) * 8;

    wmma::fragment<wmma::accumulator, 16, 16, 16, float> acc[2][2];
#pragma unroll
    for (int i = 0; i < 2; i++)
#pragma unroll
        for (int j = 0; j < 2; j++) wmma::fill_fragment(acc[i][j], 0.0f);

    const int KT = K / 32;

    auto issue = [&](int buf, int k0) {
        const __half* Ag = A + (size_t)(row0 + ar) * K + k0 + ac;
        cp16(&As[buf][ar * SA + ac], Ag);
        cp16(&As[buf][(ar + 64) * SA + ac], Ag + (size_t)64 * K);
        int brr = tid >> 3, bcc = (tid & 7) * 8;
        cp16(&Bs[buf][brr * SB + bcc], B + (size_t)(k0 + brr) * N + bcc);
    };

    issue(0, 0);
    cp_commit();

    for (int kt = 0; kt < KT; kt++) {
        int buf = kt & 1;
        if (kt + 1 < KT) {
            issue(buf ^ 1, (kt + 1) * 32);
            cp_commit();
            cp_wait<1>();
        } else {
            cp_wait<0>();
        }
        __syncthreads();
#pragma unroll
        for (int kk = 0; kk < 32; kk += 16) {
            wmma::fragment<wmma::matrix_a, 16, 16, 16, __half, wmma::row_major> fa[2];
            wmma::fragment<wmma::matrix_b, 16, 16, 16, __half, wmma::row_major> fb[2];
#pragma unroll
            for (int i = 0; i < 2; i++)
                wmma::load_matrix_sync(fa[i], &As[buf][(wm * 32 + i * 16) * SA + kk], SA);
#pragma unroll
            for (int j = 0; j < 2; j++)
                wmma::load_matrix_sync(fb[j], &Bs[buf][kk * SB + wn * 32 + j * 16], SB);
#pragma unroll
            for (int i = 0; i < 2; i++)
#pragma unroll
                for (int j = 0; j < 2; j++)
                    wmma::mma_sync(acc[i][j], fa[i], fb[j], acc[i][j]);
        }
        __syncthreads();
    }

    // epilogue: stage fp16 (reuse As, stride 72), convert to fp8.
    __half* stage = &As[0][0];   // 128 x 72 halfs = 9216 <= 10240
#pragma unroll
    for (int i = 0; i < 2; i++) {
#pragma unroll
        for (int j = 0; j < 2; j++) {
            wmma::fragment<wmma::accumulator, 16, 16, 16, __half> hf;
#pragma unroll
            for (int t = 0; t < hf.num_elements; t++)
                hf.x[t] = __float2half(acc[i][j].x[t]);
            wmma::store_matrix_sync(stage + (wm * 32 + i * 16) * SB + wn * 32 + j * 16,
                                    hf, SB, wmma::mem_row_major);
        }
    }
    __syncthreads();
    {
        int row = tid >> 1;              // 0..127
        int cb = (tid & 1) * 32;         // 0 or 32
        const __half2* sp = (const __half2*)(stage + row * SB + cb);
        unsigned short q[16];
#pragma unroll
        for (int k = 0; k < 16; k++) {
            __half2 h2 = sp[k];
            q[k] = __nv_cvt_halfraw2_to_fp8x2(*(__half2_raw*)&h2,
                                              __NV_SATFINITE, __NV_E4M3);
        }
        uint4* gp = (uint4*)(C8 + (size_t)(row0 + row) * 64 + cb);
        gp[0] = ((uint4*)q)[0];
        gp[1] = ((uint4*)q)[1];
    }
}

// ------------------------- CSR SpMM (no atomics) ----------------------------
// d=256 fp8 gather, 4-edge unroll. out(fp16) = relu(acc + b1).
__global__ void spmm256q(const unsigned char* __restrict__ Q,
                         const int* __restrict__ rowptr,
                         const int2* __restrict__ edge, const float* __restrict__ bias,
                         __half* __restrict__ out) {
    int node = (blockIdx.x * blockDim.x + threadIdx.x) >> 5;
    int lane = threadIdx.x & 31;
    if (node >= NN) return;
    int beg = rowptr[node], end = rowptr[node + 1];
    float a[8];
#pragma unroll
    for (int k = 0; k < 8; k++) a[k] = 0.f;

    int e = beg;
    for (; e + 3 < end; e += 4) {
        int2 ed[4];
        uint2 v[4];
#pragma unroll
        for (int u = 0; u < 4; u++) ed[u] = edge[e + u];
#pragma unroll
        for (int u = 0; u < 4; u++)
            v[u] = *(const uint2*)(Q + (size_t)ed[u].x * 256 + lane * 8);
#pragma unroll
        for (int u = 0; u < 4; u++) {
            float w = __int_as_float(ed[u].y);
            const unsigned short* p = (const unsigned short*)&v[u];
#pragma unroll
            for (int k = 0; k < 4; k++) {
                float2 f = fp8x2_to_f2(p[k]);
                a[2 * k + 0] += w * f.x;
                a[2 * k + 1] += w * f.y;
            }
        }
    }
    for (; e < end; e++) {
        int2 e0 = edge[e];
        float w0 = __int_as_float(e0.y);
        uint2 v0 = *(const uint2*)(Q + (size_t)e0.x * 256 + lane * 8);
        const unsigned short* p0 = (const unsigned short*)&v0;
#pragma unroll
        for (int k = 0; k < 4; k++) {
            float2 f0 = fp8x2_to_f2(p0[k]);
            a[2 * k + 0] += w0 * f0.x;
            a[2 * k + 1] += w0 * f0.y;
        }
    }
    uint4 o;
    __half2* o2 = (__half2*)&o;
#pragma unroll
    for (int k = 0; k < 4; k++) {
        float bx = bias[lane * 8 + 2 * k];
        float by = bias[lane * 8 + 2 * k + 1];
        o2[k] = __floats2half2_rn(fmaxf(a[2 * k] + bx, 0.f),
                                  fmaxf(a[2 * k + 1] + by, 0.f));
    }
    *(uint4*)(out + (size_t)node * 256 + lane * 8) = o;
}

// d=64 fp8 gather, 4-edge unroll. S(fp8) = adj T1.
__global__ void spmm64q(const unsigned char* __restrict__ Q,
                        const int* __restrict__ rowptr,
                        const int2* __restrict__ edge,
                        unsigned char* __restrict__ Sout) {
    int node = (blockIdx.x * blockDim.x + threadIdx.x) >> 5;
    int lane = threadIdx.x & 31;
    if (node >= NN) return;
    int beg = rowptr[node], end = rowptr[node + 1];
    float ax = 0.f, ay = 0.f;
    int e = beg;
    for (; e + 3 < end; e += 4) {
        int2 ed[4];
        unsigned short q[4];
#pragma unroll
        for (int u = 0; u < 4; u++) ed[u] = edge[e + u];
#pragma unroll
        for (int u = 0; u < 4; u++)
            q[u] = *(const unsigned short*)(Q + (size_t)ed[u].x * 64 + lane * 2);
#pragma unroll
        for (int u = 0; u < 4; u++) {
            float w = __int_as_float(ed[u].y);
            float2 f = fp8x2_to_f2(q[u]);
            ax += w * f.x;
            ay += w * f.y;
        }
    }
    for (; e < end; e++) {
        int2 e0 = edge[e];
        float w0 = __int_as_float(e0.y);
        float2 f = fp8x2_to_f2(*(const unsigned short*)(Q + (size_t)e0.x * 64 + lane * 2));
        ax += w0 * f.x;
        ay += w0 * f.y;
    }
    *(unsigned short*)(Sout + (size_t)node * 64 + lane * 2) = f2_to_fp8x2(ax, ay);
}

// Final: out(fp32) = log_softmax(adj S + degw*c + r), fp8 gather, 4-unroll.
__global__ void spmm64_final(const unsigned char* __restrict__ Q,
                             const int* __restrict__ rowptr,
                             const int2* __restrict__ edge, const float* __restrict__ c,
                             const float* __restrict__ r, float2* __restrict__ out) {
    int node = (blockIdx.x * blockDim.x + threadIdx.x) >> 5;
    int lane = threadIdx.x & 31;
    if (node >= NN) return;
    int beg = rowptr[node], end = rowptr[node + 1];
    float ax = 0.f, ay = 0.f, dw = 0.f;
    int e = beg;
    for (; e + 3 < end; e += 4) {
        int2 ed[4];
        unsigned short q[4];
#pragma unroll
        for (int u = 0; u < 4; u++) ed[u] = edge[e + u];
#pragma unroll
        for (int u = 0; u < 4; u++)
            q[u] = *(const unsigned short*)(Q + (size_t)ed[u].x * 64 + lane * 2);
#pragma unroll
        for (int u = 0; u < 4; u++) {
            float w = __int_as_float(ed[u].y);
            float2 f = fp8x2_to_f2(q[u]);
            ax += w * f.x;
            ay += w * f.y;
            dw += w;
        }
    }
    for (; e < end; e++) {
        int2 e0 = edge[e];
        float w0 = __int_as_float(e0.y);
        float2 f = fp8x2_to_f2(*(const unsigned short*)(Q + (size_t)e0.x * 64 + lane * 2));
        ax += w0 * f.x;
        ay += w0 * f.y;
        dw += w0;
    }
    ax += dw * c[lane * 2 + 0] + r[lane * 2 + 0];
    ay += dw * c[lane * 2 + 1] + r[lane * 2 + 1];
    float m = fmaxf(ax, ay);
#pragma unroll
    for (int o = 16; o; o >>= 1) m = fmaxf(m, __shfl_xor_sync(0xFFFFFFFFu, m, o));
    float s = __expf(ax - m) + __expf(ay - m);
#pragma unroll
    for (int o = 16; o; o >>= 1) s += __shfl_xor_sync(0xFFFFFFFFu, s, o);
    float lg = m + logf(s);
    out[(size_t)node * 32 + lane] = make_float2(ax - lg, ay - lg);
}

// ---------------------------------------------------------------------------
extern "C" void kernel_launch(void* const* d_in, const int* in_sizes, int n_in,
                              void* d_out, int out_size) {
    const float* x   = (const float*)d_in[0];
    const int*   src = (const int*)d_in[1];
    const int*   dst = (const int*)d_in[2];
    const float* ew  = (const float*)d_in[3];
    const float* W1  = (const float*)d_in[4];
    const float* b1  = (const float*)d_in[5];
    const float* W2  = (const float*)d_in[6];
    const float* b2  = (const float*)d_in[7];
    const float* W3  = (const float*)d_in[8];
    const float* r   = (const float*)d_in[9];

    unsigned char *t0q, *t1q, *sq;
    __half *h1h, *w1h, *w23h;
    float *cvec;
    int *deg, *incl, *part, *rowptr, *wofs;
    int2* edge;
    cudaGetSymbolAddress((void**)&t0q, g_T0q);
    cudaGetSymbolAddress((void**)&t1q, g_T1q);
    cudaGetSymbolAddress((void**)&sq,  g_Sq);
    cudaGetSymbolAddress((void**)&h1h, g_H1h);
    cudaGetSymbolAddress((void**)&w1h, g_W1h);
    cudaGetSymbolAddress((void**)&w23h, g_W23h);
    cudaGetSymbolAddress((void**)&cvec, g_c);
    cudaGetSymbolAddress((void**)&deg, g_deg);
    cudaGetSymbolAddress((void**)&incl, g_incl);
    cudaGetSymbolAddress((void**)&part, g_part);
    cudaGetSymbolAddress((void**)&rowptr, g_rowptr);
    cudaGetSymbolAddress((void**)&wofs, g_wofs);
    cudaGetSymbolAddress((void**)&edge, g_edge);

    const int NB = (NN + 255) / 256;            // 391
    const int WB = (int)(((size_t)NN * 32 + 255) / 256);  // 12500
    const int MB = NPAD / 128;                  // 782

    // ---- phase 1: histogram + W1 conv + W23 + c ----
    cudaMemsetAsync(deg, 0, NN * sizeof(int));
    fused_front<<<12693, 256>>>(dst, deg, (const float4*)W1, w1h, W2, W3, b2,
                                w23h, cvec);

    // ---- phase 2: prefix scan (2 kernels) ----
    scan_block<<<SCAN_B, 1024>>>(deg, incl, part);
    scan_finalize<<<NB, 256>>>(deg, incl, part, rowptr, wofs);

    // ---- phase 3: edge scatter ∥ GEMM1 (T0q = fp8(x @ W1)) ----
    fused_sg<<<14076, 256>>>(src, dst, ew, wofs, edge, x, w1h, t0q);

    // ---- gc1 aggregate: H1 = relu(spmm(T0q) + b1) ----
    spmm256q<<<WB, 256>>>(t0q, rowptr, edge, b1, h1h);

    // ---- gc2+gc3 fused weights: T1q = fp8(H1 @ W23) ----
    gemm_h64q<<<MB, 256>>>(h1h, w23h, t1q, 256);

    // ---- S = adj T1 (fp8) ----
    spmm64q<<<WB, 256>>>(t1q, rowptr, edge, sq);

    // ---- out = log_softmax(adj S + degw*c + r) ----
    spmm64_final<<<WB, 256>>>(sq, rowptr, edge, cvec, r, (float2*)d_out);
}